// round 2
// baseline (speedup 1.0000x reference)
#include <cuda_runtime.h>
#include <math.h>

#define NV   7
#define CIN  512
#define HH   64
#define WW   112
#define HWSZ (HH*WW)      // 7168
#define DM   128
#define PP   36864
#define VD   4
#define VH   96
#define VW   96
#define OC   64
#define BNEPS 1e-5f

// ---------------- scratch (device globals; no allocations) ----------------
__device__ float g_feat[NV * HWSZ * DM];   // [n][hw][d]   25.7 MB
__device__ float g_fused[PP * DM];         // [p][c]       18.9 MB
__device__ float g_h2[PP * DM];            // [voxel][c]   18.9 MB (channel-last z,y,x,c)
__device__ float g_h3[PP * OC];            // [voxel][o]    9.4 MB
__device__ float g_wt[5*5*DM*5*OC];        // [kd][kh][c][kw][o]  4.1 MB

// ---------------- Kernel 1: projection GEMM + BN1 + ReLU ----------------
// feat[m][d] = relu(bn1( sum_k img[n][k][hw] * wproj[d][k] + bproj[d] ))
// m = n*7168 + hw, M=50176, K=512, N=128.  BM=64, BN=128, BK=16, 128 threads.
__global__ __launch_bounds__(128) void k1_proj(
    const float* __restrict__ img, const float* __restrict__ wproj,
    const float* __restrict__ bproj,
    const float* __restrict__ g1, const float* __restrict__ bb1,
    const float* __restrict__ m1, const float* __restrict__ v1)
{
    __shared__ __align__(16) float As[16][64];
    __shared__ __align__(16) float Bs[16][128];

    const int m0  = blockIdx.x * 64;
    const int n   = m0 / HWSZ;          // tile never crosses view boundary (7168%64==0)
    const int hw0 = m0 % HWSZ;
    const int tid = threadIdx.x;
    const int tx = tid & 15, ty = tid >> 4;   // c0 = tx*8, r0 = ty*8
    const int r0 = ty * 8, c0 = tx * 8;

    float acc[8][8];
    #pragma unroll
    for (int r = 0; r < 8; r++)
        #pragma unroll
        for (int c = 0; c < 8; c++) acc[r][c] = 0.f;

    const int li = tid & 63;
    const int jg = tid >> 6;

    for (int k0 = 0; k0 < CIN; k0 += 16) {
        __syncthreads();
        // A tile: [64 m][16 k], gmem coalesced along m
        {
            const float* Ab = img + ((size_t)n * CIN + k0 + jg * 8) * HWSZ + hw0 + li;
            #pragma unroll
            for (int jj = 0; jj < 8; jj++)
                As[jg * 8 + jj][li] = Ab[(size_t)jj * HWSZ];
        }
        // B tile: Bs[k][d] = wproj[d][k0+k]
        {
            const float* Bb = wproj + (size_t)tid * CIN + k0;
            #pragma unroll
            for (int jj = 0; jj < 16; jj += 4) {
                float4 t = *(const float4*)(Bb + jj);
                Bs[jj    ][tid] = t.x;
                Bs[jj + 1][tid] = t.y;
                Bs[jj + 2][tid] = t.z;
                Bs[jj + 3][tid] = t.w;
            }
        }
        __syncthreads();
        #pragma unroll
        for (int j = 0; j < 16; j++) {
            float a[8], b[8];
            *(float4*)(a)     = *(const float4*)&As[j][r0];
            *(float4*)(a + 4) = *(const float4*)&As[j][r0 + 4];
            *(float4*)(b)     = *(const float4*)&Bs[j][c0];
            *(float4*)(b + 4) = *(const float4*)&Bs[j][c0 + 4];
            #pragma unroll
            for (int r = 0; r < 8; r++)
                #pragma unroll
                for (int c = 0; c < 8; c++)
                    acc[r][c] += a[r] * b[c];
        }
    }

    // epilogue: bias + BN1 + ReLU
    float sc[8], sh[8];
    #pragma unroll
    for (int c = 0; c < 8; c++) {
        int d = c0 + c;
        float s = g1[d] * rsqrtf(v1[d] + BNEPS);
        sc[c] = s;
        sh[c] = (bproj[d] - m1[d]) * s + bb1[d];
    }
    #pragma unroll
    for (int r = 0; r < 8; r++) {
        float o[8];
        #pragma unroll
        for (int c = 0; c < 8; c++)
            o[c] = fmaxf(acc[r][c] * sc[c] + sh[c], 0.f);
        float* dst = &g_feat[(size_t)(m0 + r0 + r) * DM + c0];
        *(float4*)(dst)     = *(float4*)(o);
        *(float4*)(dst + 4) = *(float4*)(o + 4);
    }
}

// ---------------- Kernel 2: gather + masked softmax fusion ----------------
// one block per p (128 threads = d), 7 views in registers
// NOTE: valid is int32 (harness materializes bool as int32)
__global__ __launch_bounds__(128) void k2_fuse(
    const int* __restrict__ xi, const int* __restrict__ yi,
    const int* __restrict__ valid)
{
    const int p = blockIdx.x;
    const int d = threadIdx.x;
    float vv[NV];
    #pragma unroll
    for (int n = 0; n < NV; n++) {
        float val = 0.f;
        if (valid[n * PP + p]) {   // uniform per block
            int lin = yi[n * PP + p] * WW + xi[n * PP + p];
            val = g_feat[((size_t)(n * HWSZ + lin)) * DM + d];
        }
        vv[n] = val;
    }
    float mx = vv[0];
    #pragma unroll
    for (int n = 1; n < NV; n++) mx = fmaxf(mx, vv[n]);
    float s = 0.f, ws = 0.f;
    #pragma unroll
    for (int n = 0; n < NV; n++) {
        float e = expf(vv[n] - mx);
        s += e;
        ws += e * vv[n];
    }
    g_fused[(size_t)p * DM + d] = ws / s;
}

// ---------------- Kernel 3: 1x1 GEMM (128->128) + BN2 + ReLU ----------------
// h2[p][o] = relu(bn2( sum_c fused[p][c]*w3a[o][c] + b3a[o] )), M=36864,K=128,N=128
__global__ __launch_bounds__(128) void k3_mix(
    const float* __restrict__ w3a, const float* __restrict__ b3a,
    const float* __restrict__ g2, const float* __restrict__ bb2,
    const float* __restrict__ m2, const float* __restrict__ v2)
{
    __shared__ __align__(16) float As[16][64];
    __shared__ __align__(16) float Bs[16][128];

    const int m0  = blockIdx.x * 64;
    const int tid = threadIdx.x;
    const int tx = tid & 15, ty = tid >> 4;
    const int r0 = ty * 8, c0 = tx * 8;

    float acc[8][8];
    #pragma unroll
    for (int r = 0; r < 8; r++)
        #pragma unroll
        for (int c = 0; c < 8; c++) acc[r][c] = 0.f;

    const int mm = tid & 63;
    const int j0 = (tid >> 6) * 8;

    for (int k0 = 0; k0 < DM; k0 += 16) {
        __syncthreads();
        {
            const float* Ab = g_fused + (size_t)(m0 + mm) * DM + k0 + j0;
            float4 t0 = *(const float4*)Ab;
            float4 t1 = *(const float4*)(Ab + 4);
            As[j0    ][mm] = t0.x; As[j0 + 1][mm] = t0.y;
            As[j0 + 2][mm] = t0.z; As[j0 + 3][mm] = t0.w;
            As[j0 + 4][mm] = t1.x; As[j0 + 5][mm] = t1.y;
            As[j0 + 6][mm] = t1.z; As[j0 + 7][mm] = t1.w;
        }
        {
            const float* Bb = w3a + (size_t)tid * DM + k0;
            #pragma unroll
            for (int jj = 0; jj < 16; jj += 4) {
                float4 t = *(const float4*)(Bb + jj);
                Bs[jj    ][tid] = t.x;
                Bs[jj + 1][tid] = t.y;
                Bs[jj + 2][tid] = t.z;
                Bs[jj + 3][tid] = t.w;
            }
        }
        __syncthreads();
        #pragma unroll
        for (int j = 0; j < 16; j++) {
            float a[8], b[8];
            *(float4*)(a)     = *(const float4*)&As[j][r0];
            *(float4*)(a + 4) = *(const float4*)&As[j][r0 + 4];
            *(float4*)(b)     = *(const float4*)&Bs[j][c0];
            *(float4*)(b + 4) = *(const float4*)&Bs[j][c0 + 4];
            #pragma unroll
            for (int r = 0; r < 8; r++)
                #pragma unroll
                for (int c = 0; c < 8; c++)
                    acc[r][c] += a[r] * b[c];
        }
    }

    float sc[8], sh[8];
    #pragma unroll
    for (int c = 0; c < 8; c++) {
        int d = c0 + c;
        float s = g2[d] * rsqrtf(v2[d] + BNEPS);
        sc[c] = s;
        sh[c] = (b3a[d] - m2[d]) * s + bb2[d];
    }
    #pragma unroll
    for (int r = 0; r < 8; r++) {
        float o[8];
        #pragma unroll
        for (int c = 0; c < 8; c++)
            o[c] = fmaxf(acc[r][c] * sc[c] + sh[c], 0.f);
        float* dst = &g_h2[(size_t)(m0 + r0 + r) * DM + c0];
        *(float4*)(dst)     = *(float4*)(o);
        *(float4*)(dst + 4) = *(float4*)(o + 4);
    }
}

// ---------------- weight transpose: w3b[o][c][kd][kh][kw] -> [kd][kh][c][kw][o] ----
__global__ void k_wt(const float* __restrict__ w3b)
{
    int idx = blockIdx.x * 256 + threadIdx.x;
    const int TOT = OC * DM * 125;
    if (idx >= TOT) return;
    int kw = idx % 5;
    int kh = (idx / 5) % 5;
    int kd = (idx / 25) % 5;
    int c  = (idx / 125) % DM;
    int o  = idx / (125 * DM);
    g_wt[((((size_t)(kd * 5 + kh) * DM + c) * 5 + kw) * OC) + o] = w3b[idx];
}

// ---------------- Kernel 4: direct 5x5x5 conv (128->64) + BN3 + ReLU ----------
// grid (6,6,4): 16x16 (y,x) tile, one z slice, all 64 oc.
// thread = 8 consecutive x * 8 oc -> 64 fp32 accumulators.
__global__ __launch_bounds__(256) void k4_conv(
    const float* __restrict__ b3b,
    const float* __restrict__ g3, const float* __restrict__ bb3,
    const float* __restrict__ m3, const float* __restrict__ v3)
{
    __shared__ __align__(16) float s_in[VD][4][20][28];  // [z][c][y][x-pad]
    __shared__ __align__(16) float s_w[4][5][OC];        // [c][kw][o]

    const int z  = blockIdx.z;
    const int by = blockIdx.y * 16, bx = blockIdx.x * 16;
    const int tid = threadIdx.x;
    const int og  = tid >> 5;             // oc group (8 oc)
    const int sp  = tid & 31;
    const int ly  = sp >> 1;              // 0..15
    const int lxh = (sp & 1) << 3;        // 0 or 8

    float acc[8][8];
    #pragma unroll
    for (int j = 0; j < 8; j++)
        #pragma unroll
        for (int o = 0; o < 8; o++) acc[j][o] = 0.f;

    for (int cb = 0; cb < DM; cb += 4) {
        __syncthreads();
        // stage input tile (4 channels, all z, 20x20 halo), float4 per (z,y,x)
        #pragma unroll 1
        for (int i = tid; i < VD * 20 * 20; i += 256) {
            int xx = i % 20;
            int yy = (i / 20) % 20;
            int zz = i / 400;
            int gy = by + yy - 2, gx = bx + xx - 2;
            float4 val = make_float4(0.f, 0.f, 0.f, 0.f);
            if ((unsigned)gy < VH && (unsigned)gx < VW)
                val = *(const float4*)&g_h2[(((size_t)zz * VH + gy) * VW + gx) * DM + cb];
            s_in[zz][0][yy][xx] = val.x;
            s_in[zz][1][yy][xx] = val.y;
            s_in[zz][2][yy][xx] = val.z;
            s_in[zz][3][yy][xx] = val.w;
        }
        __syncthreads();

        #pragma unroll 1
        for (int kd = 0; kd < 5; kd++) {
            int zi = z + kd - 2;
            if ((unsigned)zi >= VD) continue;   // uniform over block
            #pragma unroll 1
            for (int kh = 0; kh < 5; kh++) {
                __syncthreads();
                // stage weights [4c][5kw][64o]: fully contiguous in g_wt
                const float* wsrc = g_wt + ((size_t)(kd * 5 + kh) * DM + cb) * 5 * OC;
                #pragma unroll 1
                for (int i = tid; i < 4 * 5 * OC; i += 256)
                    ((float*)s_w)[i] = wsrc[i];
                __syncthreads();

                #pragma unroll
                for (int c = 0; c < 4; c++) {
                    const float* row = &s_in[zi][c][ly + kh][lxh];
                    float r[12];
                    float4 t;
                    t = *(const float4*)(row);     r[0]=t.x; r[1]=t.y; r[2]=t.z; r[3]=t.w;
                    t = *(const float4*)(row + 4); r[4]=t.x; r[5]=t.y; r[6]=t.z; r[7]=t.w;
                    t = *(const float4*)(row + 8); r[8]=t.x; r[9]=t.y; r[10]=t.z; r[11]=t.w;
                    #pragma unroll
                    for (int kw = 0; kw < 5; kw++) {
                        float4 w0 = *(const float4*)&s_w[c][kw][og * 8];
                        float4 w1 = *(const float4*)&s_w[c][kw][og * 8 + 4];
                        float wr[8] = {w0.x, w0.y, w0.z, w0.w, w1.x, w1.y, w1.z, w1.w};
                        #pragma unroll
                        for (int j = 0; j < 8; j++) {
                            float iv = r[j + kw];
                            #pragma unroll
                            for (int o = 0; o < 8; o++)
                                acc[j][o] += iv * wr[o];
                        }
                    }
                }
            }
        }
    }

    // epilogue: + b3b, BN3, ReLU -> g_h3[voxel][oc]
    const int obase = og * 8;
    float sc[8], sh[8];
    #pragma unroll
    for (int o = 0; o < 8; o++) {
        int oc = obase + o;
        float s = g3[oc] * rsqrtf(v3[oc] + BNEPS);
        sc[o] = s;
        sh[o] = (b3b[oc] - m3[oc]) * s + bb3[oc];
    }
    const size_t vox0 = ((size_t)z * VH + by + ly) * VW + bx + lxh;
    #pragma unroll
    for (int j = 0; j < 8; j++) {
        float o[8];
        #pragma unroll
        for (int k = 0; k < 8; k++)
            o[k] = fmaxf(acc[j][k] * sc[k] + sh[k], 0.f);
        float* dst = &g_h3[(vox0 + j) * OC + obase];
        *(float4*)(dst)     = *(float4*)(o);
        *(float4*)(dst + 4) = *(float4*)(o + 4);
    }
}

// ---------------- Kernel 5: 1x1 head (64->4) + sigmoid ----------------
// warp per voxel; output layout [co][voxel] (== concat(pred[:,:3], pred[:,3:]))
__global__ __launch_bounds__(256) void k5_head(
    const float* __restrict__ w3c, const float* __restrict__ b3c,
    float* __restrict__ out)
{
    int warp = (blockIdx.x * blockDim.x + threadIdx.x) >> 5;
    int lane = threadIdx.x & 31;
    if (warp >= PP) return;
    const float* hrow = g_h3 + (size_t)warp * OC;
    float a0 = hrow[lane], a1 = hrow[lane + 32];

    float r0 = a0 * w3c[0 * OC + lane] + a1 * w3c[0 * OC + lane + 32];
    float r1 = a0 * w3c[1 * OC + lane] + a1 * w3c[1 * OC + lane + 32];
    float r2 = a0 * w3c[2 * OC + lane] + a1 * w3c[2 * OC + lane + 32];
    float r3 = a0 * w3c[3 * OC + lane] + a1 * w3c[3 * OC + lane + 32];
    #pragma unroll
    for (int off = 16; off; off >>= 1) {
        r0 += __shfl_xor_sync(0xffffffffu, r0, off);
        r1 += __shfl_xor_sync(0xffffffffu, r1, off);
        r2 += __shfl_xor_sync(0xffffffffu, r2, off);
        r3 += __shfl_xor_sync(0xffffffffu, r3, off);
    }
    if (lane == 0) {
        out[0 * PP + warp] = 1.f / (1.f + expf(-(r0 + b3c[0])));
        out[1 * PP + warp] = 1.f / (1.f + expf(-(r1 + b3c[1])));
        out[2 * PP + warp] = 1.f / (1.f + expf(-(r2 + b3c[2])));
        out[3 * PP + warp] = 1.f / (1.f + expf(-(r3 + b3c[3])));
    }
}

// ---------------- launch ----------------
extern "C" void kernel_launch(void* const* d_in, const int* in_sizes, int n_in,
                              void* d_out, int out_size)
{
    const float* img   = (const float*)d_in[0];
    const int*   xi    = (const int*)d_in[1];
    const int*   yi    = (const int*)d_in[2];
    const int*   valid = (const int*)d_in[3];   // bool -> int32 in harness
    const float* wproj = (const float*)d_in[4];
    const float* bproj = (const float*)d_in[5];
    const float* bn1g = (const float*)d_in[6];
    const float* bn1b = (const float*)d_in[7];
    const float* bn1m = (const float*)d_in[8];
    const float* bn1v = (const float*)d_in[9];
    const float* w3a  = (const float*)d_in[10];
    const float* b3a  = (const float*)d_in[11];
    const float* bn2g = (const float*)d_in[12];
    const float* bn2b = (const float*)d_in[13];
    const float* bn2m = (const float*)d_in[14];
    const float* bn2v = (const float*)d_in[15];
    const float* w3b  = (const float*)d_in[16];
    const float* b3b  = (const float*)d_in[17];
    const float* bn3g = (const float*)d_in[18];
    const float* bn3b = (const float*)d_in[19];
    const float* bn3m = (const float*)d_in[20];
    const float* bn3v = (const float*)d_in[21];
    const float* w3c  = (const float*)d_in[22];
    const float* b3c  = (const float*)d_in[23];
    float* out = (float*)d_out;

    k_wt<<<(OC * DM * 125 + 255) / 256, 256>>>(w3b);
    k1_proj<<<(NV * HWSZ) / 64, 128>>>(img, wproj, bproj, bn1g, bn1b, bn1m, bn1v);
    k2_fuse<<<PP, 128>>>(xi, yi, valid);
    k3_mix<<<PP / 64, 128>>>(w3a, b3a, bn2g, bn2b, bn2m, bn2v);
    k4_conv<<<dim3(VW / 16, VH / 16, VD), 256>>>(b3b, bn3g, bn3b, bn3m, bn3v);
    k5_head<<<(PP + 7) / 8, 256>>>(w3c, b3c, out);
}